// round 16
// baseline (speedup 1.0000x reference)
#include <cuda_runtime.h>
#include <cuda_fp16.h>
#include <math.h>
#include <stdint.h>

#define D_MODEL   1024
#define NH        16
#define DH        64
#define BATCH     2
#define SEQ       2048
#define MTOT      4096

// ---------------- device scratch (no allocations allowed) ----------------
__device__ __half g_tw[4][D_MODEL*D_MODEL];                 // ternary W fp16 [n][k]
__device__ __half g_xh[MTOT*D_MODEL], g_xl[MTOT*D_MODEL];   // split activations
__device__ __half g_qh[MTOT*D_MODEL], g_ql[MTOT*D_MODEL];   // [B,H,S,Dh], pre-scaled 1/8
__device__ __half g_kh[MTOT*D_MODEL], g_kl[MTOT*D_MODEL];   // [B,H,S,Dh]
__device__ __half g_vth[MTOT*D_MODEL], g_vtl[MTOT*D_MODEL]; // [B,H,Dh,S]
__device__ __half g_ah[MTOT*D_MODEL], g_al[MTOT*D_MODEL];   // attn out [B,S,D] split
__device__ float g_partial[4*64];
__device__ float g_thresh[4];

// ---------------- warp-MMA primitives (sm_80+, valid on sm_103 family) ----
__device__ __forceinline__ uint32_t smem_u32(const void* p){
    uint32_t a;
    asm("{ .reg .u64 t; cvta.to.shared.u64 t, %1; cvt.u32.u64 %0, t; }" : "=r"(a) : "l"(p));
    return a;
}
__device__ __forceinline__ void mma16816(float* c, const uint32_t* a, const uint32_t* b){
    asm volatile("mma.sync.aligned.m16n8k16.row.col.f32.f16.f16.f32 "
        "{%0,%1,%2,%3}, {%4,%5,%6,%7}, {%8,%9}, {%0,%1,%2,%3};"
        : "+f"(c[0]), "+f"(c[1]), "+f"(c[2]), "+f"(c[3])
        : "r"(a[0]), "r"(a[1]), "r"(a[2]), "r"(a[3]), "r"(b[0]), "r"(b[1]));
}
__device__ __forceinline__ void ldsm4(uint32_t* r, uint32_t a){
    asm volatile("ldmatrix.sync.aligned.m8n8.x4.shared.b16 {%0,%1,%2,%3}, [%4];"
        : "=r"(r[0]), "=r"(r[1]), "=r"(r[2]), "=r"(r[3]) : "r"(a));
}
__device__ __forceinline__ void cpasync16(uint32_t dst, const void* src){
    asm volatile("cp.async.cg.shared.global [%0], [%1], 16;" :: "r"(dst), "l"(src));
}
#define CP_COMMIT() asm volatile("cp.async.commit_group;" ::: "memory")
#define CP_WAIT0()  asm volatile("cp.async.wait_group 0;" ::: "memory")

__device__ __forceinline__ uint32_t pack2(float a, float b){
    __half2 h = __floats2half2_rn(a, b);
    return *reinterpret_cast<uint32_t*>(&h);
}
__device__ __forceinline__ void split_store(__half* ph, __half* pl, size_t off,
                                            float v0, float v1){
    __half h0 = __float2half_rn(v0), h1 = __float2half_rn(v1);
    __half l0 = __float2half_rn(v0 - __half2float(h0));
    __half l1 = __float2half_rn(v1 - __half2float(h1));
    *(__half2*)(ph + off) = __halves2half2(h0, h1);
    *(__half2*)(pl + off) = __halves2half2(l0, l1);
}

// ---------------- abs-mean (deterministic 2-stage reduction) --------------
__global__ void absmean_partial(const float* __restrict__ w0, const float* __restrict__ w1,
                                const float* __restrict__ w2, const float* __restrict__ w3) {
    const float* w = (blockIdx.y == 0) ? w0 : (blockIdx.y == 1) ? w1 : (blockIdx.y == 2) ? w2 : w3;
    __shared__ float sm[256];
    int base = blockIdx.x * 16384;
    float s = 0.f;
    for (int i = threadIdx.x; i < 16384; i += 256) s += fabsf(w[base + i]);
    sm[threadIdx.x] = s;
    __syncthreads();
    for (int off = 128; off > 0; off >>= 1) {
        if (threadIdx.x < off) sm[threadIdx.x] += sm[threadIdx.x + off];
        __syncthreads();
    }
    if (threadIdx.x == 0) g_partial[blockIdx.y * 64 + blockIdx.x] = sm[0];
}

__global__ void absmean_final() {
    int t = threadIdx.x;
    if (t < 4) {
        float s = 0.f;
        for (int i = 0; i < 64; i++) s += g_partial[t * 64 + i];
        g_thresh[t] = s / (float)(D_MODEL * D_MODEL);
    }
}

// ---------------- ternarize -> fp16, [n][k] layout ------------------------
__global__ void ternarize_h(const float* __restrict__ w0, const float* __restrict__ w1,
                            const float* __restrict__ w2, const float* __restrict__ w3) {
    int z = blockIdx.y;
    const float* w = (z == 0) ? w0 : (z == 1) ? w1 : (z == 2) ? w2 : w3;
    float th = g_thresh[z];
    int i = blockIdx.x * 256 + threadIdx.x;
    float v = w[i];
    g_tw[z][i] = __float2half_rn((fabsf(v) > th) ? (v > 0.f ? 1.f : -1.f) : 0.f);
}

// ---------------- split fp32 activation -> fp16 hi/lo ---------------------
__global__ void split_act(const float* __restrict__ x) {
    int i = (blockIdx.x * 256 + threadIdx.x) * 4;
    float4 v = *(const float4*)(x + i);
    __half h0 = __float2half_rn(v.x), h1 = __float2half_rn(v.y);
    __half h2 = __float2half_rn(v.z), h3 = __float2half_rn(v.w);
    __half l0 = __float2half_rn(v.x - __half2float(h0));
    __half l1 = __float2half_rn(v.y - __half2float(h1));
    __half l2 = __float2half_rn(v.z - __half2float(h2));
    __half l3 = __float2half_rn(v.w - __half2float(h3));
    ((__half2*)g_xh)[i/2]     = __halves2half2(h0, h1);
    ((__half2*)g_xh)[i/2 + 1] = __halves2half2(h2, h3);
    ((__half2*)g_xl)[i/2]     = __halves2half2(l0, l1);
    ((__half2*)g_xl)[i/2 + 1] = __halves2half2(l2, l3);
}

// ---------------- HMMA GEMM, 128x128 tile, K=1024, split operands ---------
// MODE 0: C = (Ah+Al) @ W^T -> fp32 o_f [4096,1024]
// MODE 1: Q = (Xh+Xl) @ Wq^T * 0.125 -> split [B,H,S,Dh]
// MODE 2: K likewise (no scale)
// MODE 3: V^T = Wv @ (Xh+Xl)^T -> split [B,H,Dh,S]   (A=W, B split)
// 256 threads = 8 warps (4m x 2n), warp tile 32x64, k-step 32, cp.async x2 buf
template<int MODE>
__global__ void __launch_bounds__(256) mma_gemm(
    const __half* __restrict__ A0, const __half* __restrict__ A1,
    const __half* __restrict__ B0, const __half* __restrict__ B1,
    __half* __restrict__ o_h, __half* __restrict__ o_l, float* __restrict__ o_f)
{
    extern __shared__ char smraw[];
    uint32_t smb = smem_u32(smraw);
    const int TSZ = 10240, BUF = 3 * TSZ;            // [128][40] halves per slot
    int tid = threadIdx.x, lane = tid & 31, w = tid >> 5;
    int wm = w >> 1, wn = w & 1;
    int n0 = blockIdx.x * 128, m0 = blockIdx.y * 128;

    const __half* s0 = A0 + (size_t)m0 * D_MODEL;
    const __half* s1 = (MODE < 3) ? (A1 + (size_t)m0 * D_MODEL)
                                  : (B1 + (size_t)n0 * D_MODEL);
    const __half* s2 = B0 + (size_t)n0 * D_MODEL;
    int lrow = tid >> 1, qb = (tid & 1) * 2;

    auto issue = [&](int c, int bufo){
        int k0 = c * 32;
        #pragma unroll
        for (int q = qb; q < qb + 2; q++){
            uint32_t dst = smb + bufo + lrow * 80 + q * 16;
            const __half* off0 = s0 + (size_t)lrow * D_MODEL + k0 + q * 8;
            const __half* off1 = s1 + (size_t)lrow * D_MODEL + k0 + q * 8;
            const __half* off2 = s2 + (size_t)lrow * D_MODEL + k0 + q * 8;
            cpasync16(dst,           off0);
            cpasync16(dst + TSZ,     off1);
            cpasync16(dst + 2 * TSZ, off2);
        }
    };

    float acc[2][8][4];
    #pragma unroll
    for (int i = 0; i < 2; i++)
        #pragma unroll
        for (int j = 0; j < 8; j++)
            #pragma unroll
            for (int t = 0; t < 4; t++) acc[i][j][t] = 0.f;

    issue(0, 0); CP_COMMIT();

    for (int c = 0; c < 32; c++){
        int bufo = (c & 1) * BUF;
        CP_WAIT0();
        __syncthreads();
        if (c + 1 < 32){ issue(c + 1, ((c + 1) & 1) * BUF); CP_COMMIT(); }
        #pragma unroll
        for (int f = 0; f < 2; f++){
            uint32_t a0f[2][4], a1f[2][4];
            #pragma unroll
            for (int i = 0; i < 2; i++){
                uint32_t arow = 32 * wm + 16 * i + (lane & 15);
                uint32_t acol = ((lane >> 4) * 8 + 16 * f) * 2;
                ldsm4(a0f[i], smb + bufo + arow * 80 + acol);
                if (MODE < 3) ldsm4(a1f[i], smb + bufo + TSZ + arow * 80 + acol);
            }
            #pragma unroll
            for (int jp = 0; jp < 4; jp++){
                uint32_t brow = 64 * wn + 16 * jp + (lane & 7) + ((lane >> 4) << 3);
                uint32_t bcol = (16 * f + ((lane >> 3) & 1) * 8) * 2;
                uint32_t bb[4];
                ldsm4(bb, smb + bufo + 2 * TSZ + brow * 80 + bcol);
                if (MODE < 3){
                    #pragma unroll
                    for (int i = 0; i < 2; i++){
                        mma16816(acc[i][2*jp],   a0f[i], bb);
                        mma16816(acc[i][2*jp],   a1f[i], bb);
                        mma16816(acc[i][2*jp+1], a0f[i], bb + 2);
                        mma16816(acc[i][2*jp+1], a1f[i], bb + 2);
                    }
                } else {
                    uint32_t b2[4];
                    ldsm4(b2, smb + bufo + TSZ + brow * 80 + bcol);
                    #pragma unroll
                    for (int i = 0; i < 2; i++){
                        mma16816(acc[i][2*jp],   a0f[i], bb);
                        mma16816(acc[i][2*jp],   a0f[i], b2);
                        mma16816(acc[i][2*jp+1], a0f[i], bb + 2);
                        mma16816(acc[i][2*jp+1], a0f[i], b2 + 2);
                    }
                }
            }
        }
    }

    // epilogue: C frag (r, 2c) rows r,r+8
    int r = lane >> 2, cx = (lane & 3) * 2;
    const float sc = (MODE == 1) ? 0.125f : 1.0f;
    #pragma unroll
    for (int i = 0; i < 2; i++){
        int gm = m0 + 32 * wm + 16 * i + r;
        #pragma unroll
        for (int j = 0; j < 8; j++){
            int gn = n0 + 64 * wn + 8 * j + cx;
            float v0 = acc[i][j][0] * sc, v1 = acc[i][j][1] * sc;
            float v2 = acc[i][j][2] * sc, v3 = acc[i][j][3] * sc;
            if (MODE == 0){
                *(float2*)(o_f + (size_t)gm * D_MODEL + gn)       = make_float2(v0, v1);
                *(float2*)(o_f + (size_t)(gm + 8) * D_MODEL + gn) = make_float2(v2, v3);
            } else if (MODE < 3){
                int hh = gn >> 6, d = gn & 63;
                int b0i = gm >> 11, ss0 = gm & 2047;
                size_t off0 = (((size_t)(b0i * NH + hh)) * SEQ + ss0) * DH + d;
                split_store(o_h, o_l, off0, v0, v1);
                size_t off1 = off0 + 8 * DH;   // gm+8 -> s+8, same b
                split_store(o_h, o_l, off1, v2, v3);
            } else {
                int hh = gm >> 6, d = gm & 63;
                int b0i = gn >> 11, ss0 = gn & 2047;
                size_t off0 = (((size_t)(b0i * NH + hh)) * DH + d) * SEQ + ss0;
                split_store(o_h, o_l, off0, v0, v1);
                size_t off1 = off0 + 8 * SEQ;  // gm+8 -> d+8, same head
                split_store(o_h, o_l, off1, v2, v3);
            }
        }
    }
}

// ---------------- HMMA flash attention, 128q x 128k, P in registers -------
// 256 threads = 8 warps, warp = 16 q-rows x 128 cols. cp.async double buffer.
#define FK_H 0
#define FK_L 18432
#define FV_H 36864
#define FV_L 54272
#define FBUF 71680

__global__ void __launch_bounds__(256) mma_flash(
    const __half* __restrict__ qh, const __half* __restrict__ ql,
    const __half* __restrict__ kh, const __half* __restrict__ kl,
    const __half* __restrict__ vh, const __half* __restrict__ vl,
    __half* __restrict__ oh, __half* __restrict__ ol)
{
    extern __shared__ char smraw[];
    uint32_t smb = smem_u32(smraw);
    int tid = threadIdx.x, lane = tid & 31, w = tid >> 5;
    int q0 = blockIdx.x * 128, h = blockIdx.y, b = blockIdx.z;
    size_t hb = ((size_t)(b * NH + h)) * SEQ * DH;

    // K/V tile loader: K [128][64] stride 72h, V^T [64][128] stride 136h
    auto load_tile = [&](int kt, int bufo){
        #pragma unroll
        for (int i = 0; i < 4; i++){
            int idx = tid + i * 256;
            int row = idx >> 3, q = idx & 7;
            uint32_t d = smb + bufo + row * 144 + q * 16;
            const __half* g = kh + hb + (size_t)(kt * 128 + row) * DH + q * 8;
            cpasync16(d, g);
            cpasync16(d + (FK_L - FK_H), kl + hb + (size_t)(kt * 128 + row) * DH + q * 8);
        }
        #pragma unroll
        for (int i = 0; i < 4; i++){
            int idx = tid + i * 256;
            int dd = idx >> 4, q = idx & 15;
            uint32_t d = smb + bufo + FV_H + dd * 272 + q * 16;
            cpasync16(d, vh + hb + (size_t)dd * SEQ + kt * 128 + q * 8);
            cpasync16(d + (FV_L - FV_H), vl + hb + (size_t)dd * SEQ + kt * 128 + q * 8);
        }
    };

    // prologue: Q -> buf1 K region, tile0 -> buf0
    #pragma unroll
    for (int i = 0; i < 4; i++){
        int idx = tid + i * 256;
        int row = idx >> 3, q = idx & 7;
        uint32_t d = smb + FBUF + row * 144 + q * 16;
        cpasync16(d, qh + hb + (size_t)(q0 + row) * DH + q * 8);
        cpasync16(d + 18432, ql + hb + (size_t)(q0 + row) * DH + q * 8);
    }
    load_tile(0, 0);
    CP_COMMIT();
    CP_WAIT0();
    __syncthreads();

    // Q fragments to registers (warp w: rows 16w..16w+15)
    uint32_t qfh[4][4], qfl[4][4];
    #pragma unroll
    for (int f = 0; f < 4; f++){
        uint32_t a = (16 * w + (lane & 15)) * 144 + ((lane >> 4) * 8 + 16 * f) * 2;
        ldsm4(qfh[f], smb + FBUF + a);
        ldsm4(qfl[f], smb + FBUF + 18432 + a);
    }
    __syncthreads();
    load_tile(1, FBUF);
    CP_COMMIT();

    float o[8][4];
    #pragma unroll
    for (int j = 0; j < 8; j++)
        #pragma unroll
        for (int t = 0; t < 4; t++) o[j][t] = 0.f;
    float mi0 = -1e30f, mi1 = -1e30f, ls0 = 0.f, ls1 = 0.f;

    for (int kt = 0; kt < 16; kt++){
        int bufo = (kt & 1) * FBUF;
        if (kt > 0) CP_WAIT0();
        __syncthreads();
        if (kt + 1 < 16){ load_tile(kt + 1, ((kt + 1) & 1) * FBUF); CP_COMMIT(); }

        // S = Qh Kh + Ql Kh + Qh Kl
        float s[16][4];
        #pragma unroll
        for (int j = 0; j < 16; j++)
            #pragma unroll
            for (int t = 0; t < 4; t++) s[j][t] = 0.f;
        #pragma unroll
        for (int f = 0; f < 4; f++){
            #pragma unroll
            for (int jp = 0; jp < 8; jp++){
                uint32_t a = bufo + (16 * jp + (lane & 7) + ((lane >> 4) << 3)) * 144
                           + (16 * f + ((lane >> 3) & 1) * 8) * 2;
                uint32_t bh4[4], bl4[4];
                ldsm4(bh4, smb + a);
                ldsm4(bl4, smb + a + (FK_L - FK_H));
                mma16816(s[2*jp],   qfh[f], bh4);
                mma16816(s[2*jp],   qfl[f], bh4);
                mma16816(s[2*jp],   qfh[f], bl4);
                mma16816(s[2*jp+1], qfh[f], bh4 + 2);
                mma16816(s[2*jp+1], qfl[f], bh4 + 2);
                mma16816(s[2*jp+1], qfh[f], bl4 + 2);
            }
        }

        // online softmax (rows r=lane>>2 and r+8; quad = lanes xor 1,2)
        float m0 = mi0, m1 = mi1;
        #pragma unroll
        for (int j = 0; j < 16; j++){
            m0 = fmaxf(m0, fmaxf(s[j][0], s[j][1]));
            m1 = fmaxf(m1, fmaxf(s[j][2], s[j][3]));
        }
        m0 = fmaxf(m0, __shfl_xor_sync(0xffffffffu, m0, 1));
        m0 = fmaxf(m0, __shfl_xor_sync(0xffffffffu, m0, 2));
        m1 = fmaxf(m1, __shfl_xor_sync(0xffffffffu, m1, 1));
        m1 = fmaxf(m1, __shfl_xor_sync(0xffffffffu, m1, 2));
        float c0 = __expf(mi0 - m0), c1 = __expf(mi1 - m1);
        mi0 = m0; mi1 = m1;
        ls0 *= c0; ls1 *= c1;
        #pragma unroll
        for (int j = 0; j < 8; j++){
            o[j][0] *= c0; o[j][1] *= c0; o[j][2] *= c1; o[j][3] *= c1;
        }
        // exp -> fp16 P (li from rounded values for consistency)
        uint32_t pa[8][4];
        #pragma unroll
        for (int j = 0; j < 16; j++){
            float p0 = __expf(s[j][0] - m0), p1 = __expf(s[j][1] - m0);
            float p2 = __expf(s[j][2] - m1), p3 = __expf(s[j][3] - m1);
            uint32_t u01 = pack2(p0, p1), u23 = pack2(p2, p3);
            __half2 h01 = *(__half2*)&u01, h23 = *(__half2*)&u23;
            ls0 += __low2float(h01) + __high2float(h01);
            ls1 += __low2float(h23) + __high2float(h23);
            pa[j >> 1][(j & 1) * 2 + 0] = u01;
            pa[j >> 1][(j & 1) * 2 + 1] = u23;
        }
        // O += P Vh + P Vl
        #pragma unroll
        for (int f = 0; f < 8; f++){
            #pragma unroll
            for (int jp = 0; jp < 4; jp++){
                uint32_t a = bufo + FV_H + (16 * jp + (lane & 7) + ((lane >> 4) << 3)) * 272
                           + (16 * f + ((lane >> 3) & 1) * 8) * 2;
                uint32_t vh4[4], vl4[4];
                ldsm4(vh4, smb + a);
                ldsm4(vl4, smb + a + (FV_L - FV_H));
                mma16816(o[2*jp],   pa[f], vh4);
                mma16816(o[2*jp],   pa[f], vl4);
                mma16816(o[2*jp+1], pa[f], vh4 + 2);
                mma16816(o[2*jp+1], pa[f], vl4 + 2);
            }
        }
    }

    // epilogue
    ls0 += __shfl_xor_sync(0xffffffffu, ls0, 1);
    ls0 += __shfl_xor_sync(0xffffffffu, ls0, 2);
    ls1 += __shfl_xor_sync(0xffffffffu, ls1, 1);
    ls1 += __shfl_xor_sync(0xffffffffu, ls1, 2);
    float i0 = 1.f / ls0, i1 = 1.f / ls1;
    int r0 = q0 + 16 * w + (lane >> 2), r1 = r0 + 8;
    #pragma unroll
    for (int j = 0; j < 8; j++){
        int d = 8 * j + (lane & 3) * 2;
        size_t off0 = ((size_t)(b * SEQ + r0)) * D_MODEL + h * DH + d;
        size_t off1 = ((size_t)(b * SEQ + r1)) * D_MODEL + h * DH + d;
        split_store(oh, ol, off0, o[j][0] * i0, o[j][1] * i0);
        split_store(oh, ol, off1, o[j][2] * i1, o[j][3] * i1);
    }
}

// ---------------- launch ---------------------------------------------------
#define GEMM_SMEM  (2 * 3 * 10240)    // 61440
#define FLASH_SMEM (2 * FBUF)         // 143360

extern "C" void kernel_launch(void* const* d_in, const int* in_sizes, int n_in,
                              void* d_out, int out_size) {
    (void)in_sizes; (void)n_in; (void)out_size;
    const float* q  = (const float*)d_in[0];
    const float* k  = (const float*)d_in[1];
    const float* v  = (const float*)d_in[2];
    const float* wq = (const float*)d_in[3];
    const float* wk = (const float*)d_in[4];
    const float* wv = (const float*)d_in[5];
    const float* wo = (const float*)d_in[6];
    float* out = (float*)d_out;

    __half *tw, *xh, *xl, *pqh, *pql, *pkh, *pkl, *pvth, *pvtl, *pah, *pal;
    cudaGetSymbolAddress((void**)&tw,   g_tw);
    cudaGetSymbolAddress((void**)&xh,   g_xh);
    cudaGetSymbolAddress((void**)&xl,   g_xl);
    cudaGetSymbolAddress((void**)&pqh,  g_qh);
    cudaGetSymbolAddress((void**)&pql,  g_ql);
    cudaGetSymbolAddress((void**)&pkh,  g_kh);
    cudaGetSymbolAddress((void**)&pkl,  g_kl);
    cudaGetSymbolAddress((void**)&pvth, g_vth);
    cudaGetSymbolAddress((void**)&pvtl, g_vtl);
    cudaGetSymbolAddress((void**)&pah,  g_ah);
    cudaGetSymbolAddress((void**)&pal,  g_al);

    cudaFuncSetAttribute(mma_gemm<0>, cudaFuncAttributeMaxDynamicSharedMemorySize, GEMM_SMEM);
    cudaFuncSetAttribute(mma_gemm<1>, cudaFuncAttributeMaxDynamicSharedMemorySize, GEMM_SMEM);
    cudaFuncSetAttribute(mma_gemm<2>, cudaFuncAttributeMaxDynamicSharedMemorySize, GEMM_SMEM);
    cudaFuncSetAttribute(mma_gemm<3>, cudaFuncAttributeMaxDynamicSharedMemorySize, GEMM_SMEM);
    cudaFuncSetAttribute(mma_flash,   cudaFuncAttributeMaxDynamicSharedMemorySize, FLASH_SMEM);

    const size_t WSZ = (size_t)D_MODEL * D_MODEL;

    absmean_partial<<<dim3(64, 4), 256>>>(wq, wk, wv, wo);
    absmean_final<<<1, 32>>>();
    ternarize_h<<<dim3(4096, 4), 256>>>(wq, wk, wv, wo);

    // Q projection
    split_act<<<4096, 256>>>(q);
    mma_gemm<1><<<dim3(8, 32), 256, GEMM_SMEM>>>(xh, xl, tw + 0 * WSZ, nullptr,
                                                 pqh, pql, nullptr);
    // K projection
    split_act<<<4096, 256>>>(k);
    mma_gemm<2><<<dim3(8, 32), 256, GEMM_SMEM>>>(xh, xl, tw + 1 * WSZ, nullptr,
                                                 pkh, pkl, nullptr);
    // V projection (transposed output)
    split_act<<<4096, 256>>>(v);
    mma_gemm<3><<<dim3(32, 8), 256, GEMM_SMEM>>>(tw + 2 * WSZ, nullptr, xh, xl,
                                                 pvth, pvtl, nullptr);
    // attention
    mma_flash<<<dim3(SEQ / 128, NH, BATCH), 256, FLASH_SMEM>>>(
        pqh, pql, pkh, pkl, pvth, pvtl, pah, pal);
    // output projection
    mma_gemm<0><<<dim3(8, 32), 256, GEMM_SMEM>>>(pah, pal, tw + 3 * WSZ, nullptr,
                                                 nullptr, nullptr, out);
}

// round 17
// speedup vs baseline: 1.0001x; 1.0001x over previous
#include <cuda_runtime.h>
#include <cuda_fp16.h>
#include <math.h>
#include <stdint.h>

#define D_MODEL   1024
#define NH        16
#define DH        64
#define BATCH     2
#define SEQ       2048
#define MTOT      4096

// ---------------- device scratch (no allocations allowed) ----------------
__device__ __half g_tw[4][D_MODEL*D_MODEL];                 // ternary W fp16 [n][k]
__device__ __half g_xh[MTOT*D_MODEL], g_xl[MTOT*D_MODEL];   // split activations
__device__ __half g_qh[MTOT*D_MODEL], g_ql[MTOT*D_MODEL];   // [B,H,S,Dh], pre-scaled 1/8
__device__ __half g_kh[MTOT*D_MODEL], g_kl[MTOT*D_MODEL];   // [B,H,S,Dh]
__device__ __half g_vth[MTOT*D_MODEL], g_vtl[MTOT*D_MODEL]; // [B,H,Dh,S]
__device__ __half g_ah[MTOT*D_MODEL], g_al[MTOT*D_MODEL];   // attn out [B,S,D] split
__device__ float g_partial[4*64];
__device__ float g_thresh[4];

// ---------------- warp-MMA primitives (sm_80+, valid on sm_103 family) ----
__device__ __forceinline__ uint32_t smem_u32(const void* p){
    uint32_t a;
    asm("{ .reg .u64 t; cvta.to.shared.u64 t, %1; cvt.u32.u64 %0, t; }" : "=r"(a) : "l"(p));
    return a;
}
__device__ __forceinline__ void mma16816(float* c, const uint32_t* a, const uint32_t* b){
    asm volatile("mma.sync.aligned.m16n8k16.row.col.f32.f16.f16.f32 "
        "{%0,%1,%2,%3}, {%4,%5,%6,%7}, {%8,%9}, {%0,%1,%2,%3};"
        : "+f"(c[0]), "+f"(c[1]), "+f"(c[2]), "+f"(c[3])
        : "r"(a[0]), "r"(a[1]), "r"(a[2]), "r"(a[3]), "r"(b[0]), "r"(b[1]));
}
__device__ __forceinline__ void ldsm4(uint32_t* r, uint32_t a){
    asm volatile("ldmatrix.sync.aligned.m8n8.x4.shared.b16 {%0,%1,%2,%3}, [%4];"
        : "=r"(r[0]), "=r"(r[1]), "=r"(r[2]), "=r"(r[3]) : "r"(a));
}
__device__ __forceinline__ void cpasync16(uint32_t dst, const void* src){
    asm volatile("cp.async.cg.shared.global [%0], [%1], 16;" :: "r"(dst), "l"(src));
}
#define CP_COMMIT() asm volatile("cp.async.commit_group;" ::: "memory")
#define CP_WAIT0()  asm volatile("cp.async.wait_group 0;" ::: "memory")

__device__ __forceinline__ uint32_t pack2(float a, float b){
    __half2 h = __floats2half2_rn(a, b);
    return *reinterpret_cast<uint32_t*>(&h);
}
__device__ __forceinline__ void split_store(__half* ph, __half* pl, size_t off,
                                            float v0, float v1){
    __half h0 = __float2half_rn(v0), h1 = __float2half_rn(v1);
    __half l0 = __float2half_rn(v0 - __half2float(h0));
    __half l1 = __float2half_rn(v1 - __half2float(h1));
    *(__half2*)(ph + off) = __halves2half2(h0, h1);
    *(__half2*)(pl + off) = __halves2half2(l0, l1);
}

// ---------------- abs-mean (deterministic 2-stage reduction) --------------
__global__ void absmean_partial(const float* __restrict__ w0, const float* __restrict__ w1,
                                const float* __restrict__ w2, const float* __restrict__ w3) {
    const float* w = (blockIdx.y == 0) ? w0 : (blockIdx.y == 1) ? w1 : (blockIdx.y == 2) ? w2 : w3;
    __shared__ float sm[256];
    int base = blockIdx.x * 16384;
    float s = 0.f;
    for (int i = threadIdx.x; i < 16384; i += 256) s += fabsf(w[base + i]);
    sm[threadIdx.x] = s;
    __syncthreads();
    for (int off = 128; off > 0; off >>= 1) {
        if (threadIdx.x < off) sm[threadIdx.x] += sm[threadIdx.x + off];
        __syncthreads();
    }
    if (threadIdx.x == 0) g_partial[blockIdx.y * 64 + blockIdx.x] = sm[0];
}

__global__ void absmean_final() {
    int t = threadIdx.x;
    if (t < 4) {
        float s = 0.f;
        for (int i = 0; i < 64; i++) s += g_partial[t * 64 + i];
        g_thresh[t] = s / (float)(D_MODEL * D_MODEL);
    }
}

// ---------------- ternarize -> fp16, [n][k] layout ------------------------
__global__ void ternarize_h(const float* __restrict__ w0, const float* __restrict__ w1,
                            const float* __restrict__ w2, const float* __restrict__ w3) {
    int z = blockIdx.y;
    const float* w = (z == 0) ? w0 : (z == 1) ? w1 : (z == 2) ? w2 : w3;
    float th = g_thresh[z];
    int i = blockIdx.x * 256 + threadIdx.x;
    float v = w[i];
    g_tw[z][i] = __float2half_rn((fabsf(v) > th) ? (v > 0.f ? 1.f : -1.f) : 0.f);
}

// ---------------- split fp32 activation -> fp16 hi/lo ---------------------
__global__ void split_act(const float* __restrict__ x) {
    int i = (blockIdx.x * 256 + threadIdx.x) * 4;
    float4 v = *(const float4*)(x + i);
    __half h0 = __float2half_rn(v.x), h1 = __float2half_rn(v.y);
    __half h2 = __float2half_rn(v.z), h3 = __float2half_rn(v.w);
    __half l0 = __float2half_rn(v.x - __half2float(h0));
    __half l1 = __float2half_rn(v.y - __half2float(h1));
    __half l2 = __float2half_rn(v.z - __half2float(h2));
    __half l3 = __float2half_rn(v.w - __half2float(h3));
    ((__half2*)g_xh)[i/2]     = __halves2half2(h0, h1);
    ((__half2*)g_xh)[i/2 + 1] = __halves2half2(h2, h3);
    ((__half2*)g_xl)[i/2]     = __halves2half2(l0, l1);
    ((__half2*)g_xl)[i/2 + 1] = __halves2half2(l2, l3);
}

// ---------------- HMMA GEMM, 128x128 tile, K=1024, split operands ---------
// MODE 0: C = (Ah+Al) @ W^T -> fp32 o_f [4096,1024]
// MODE 1: Q = (Xh+Xl) @ Wq^T * 0.125 -> split [B,H,S,Dh]
// MODE 2: K likewise (no scale)
// MODE 3: V^T = Wv @ (Xh+Xl)^T -> split [B,H,Dh,S]   (A=W, B split)
// 256 threads = 8 warps (4m x 2n), warp tile 32x64, k-step 32, cp.async x2 buf
template<int MODE>
__global__ void __launch_bounds__(256) mma_gemm(
    const __half* __restrict__ A0, const __half* __restrict__ A1,
    const __half* __restrict__ B0, const __half* __restrict__ B1,
    __half* __restrict__ o_h, __half* __restrict__ o_l, float* __restrict__ o_f)
{
    extern __shared__ char smraw[];
    uint32_t smb = smem_u32(smraw);
    const int TSZ = 10240, BUF = 3 * TSZ;            // [128][40] halves per slot
    int tid = threadIdx.x, lane = tid & 31, w = tid >> 5;
    int wm = w >> 1, wn = w & 1;
    int n0 = blockIdx.x * 128, m0 = blockIdx.y * 128;

    const __half* s0 = A0 + (size_t)m0 * D_MODEL;
    const __half* s1 = (MODE < 3) ? (A1 + (size_t)m0 * D_MODEL)
                                  : (B1 + (size_t)n0 * D_MODEL);
    const __half* s2 = B0 + (size_t)n0 * D_MODEL;
    int lrow = tid >> 1, qb = (tid & 1) * 2;

    auto issue = [&](int c, int bufo){
        int k0 = c * 32;
        #pragma unroll
        for (int q = qb; q < qb + 2; q++){
            uint32_t dst = smb + bufo + lrow * 80 + q * 16;
            const __half* off0 = s0 + (size_t)lrow * D_MODEL + k0 + q * 8;
            const __half* off1 = s1 + (size_t)lrow * D_MODEL + k0 + q * 8;
            const __half* off2 = s2 + (size_t)lrow * D_MODEL + k0 + q * 8;
            cpasync16(dst,           off0);
            cpasync16(dst + TSZ,     off1);
            cpasync16(dst + 2 * TSZ, off2);
        }
    };

    float acc[2][8][4];
    #pragma unroll
    for (int i = 0; i < 2; i++)
        #pragma unroll
        for (int j = 0; j < 8; j++)
            #pragma unroll
            for (int t = 0; t < 4; t++) acc[i][j][t] = 0.f;

    issue(0, 0); CP_COMMIT();

    for (int c = 0; c < 32; c++){
        int bufo = (c & 1) * BUF;
        CP_WAIT0();
        __syncthreads();
        if (c + 1 < 32){ issue(c + 1, ((c + 1) & 1) * BUF); CP_COMMIT(); }
        #pragma unroll
        for (int f = 0; f < 2; f++){
            uint32_t a0f[2][4], a1f[2][4];
            #pragma unroll
            for (int i = 0; i < 2; i++){
                uint32_t arow = 32 * wm + 16 * i + (lane & 15);
                uint32_t acol = ((lane >> 4) * 8 + 16 * f) * 2;
                ldsm4(a0f[i], smb + bufo + arow * 80 + acol);
                if (MODE < 3) ldsm4(a1f[i], smb + bufo + TSZ + arow * 80 + acol);
            }
            #pragma unroll
            for (int jp = 0; jp < 4; jp++){
                uint32_t brow = 64 * wn + 16 * jp + (lane & 7) + ((lane >> 4) << 3);
                uint32_t bcol = (16 * f + ((lane >> 3) & 1) * 8) * 2;
                uint32_t bb[4];
                ldsm4(bb, smb + bufo + 2 * TSZ + brow * 80 + bcol);
                if (MODE < 3){
                    #pragma unroll
                    for (int i = 0; i < 2; i++){
                        mma16816(acc[i][2*jp],   a0f[i], bb);
                        mma16816(acc[i][2*jp],   a1f[i], bb);
                        mma16816(acc[i][2*jp+1], a0f[i], bb + 2);
                        mma16816(acc[i][2*jp+1], a1f[i], bb + 2);
                    }
                } else {
                    uint32_t b2[4];
                    ldsm4(b2, smb + bufo + TSZ + brow * 80 + bcol);
                    #pragma unroll
                    for (int i = 0; i < 2; i++){
                        mma16816(acc[i][2*jp],   a0f[i], bb);
                        mma16816(acc[i][2*jp],   a0f[i], b2);
                        mma16816(acc[i][2*jp+1], a0f[i], bb + 2);
                        mma16816(acc[i][2*jp+1], a0f[i], b2 + 2);
                    }
                }
            }
        }
    }

    // epilogue: C frag (r, 2c) rows r,r+8
    int r = lane >> 2, cx = (lane & 3) * 2;
    const float sc = (MODE == 1) ? 0.125f : 1.0f;
    #pragma unroll
    for (int i = 0; i < 2; i++){
        int gm = m0 + 32 * wm + 16 * i + r;
        #pragma unroll
        for (int j = 0; j < 8; j++){
            int gn = n0 + 64 * wn + 8 * j + cx;
            float v0 = acc[i][j][0] * sc, v1 = acc[i][j][1] * sc;
            float v2 = acc[i][j][2] * sc, v3 = acc[i][j][3] * sc;
            if (MODE == 0){
                *(float2*)(o_f + (size_t)gm * D_MODEL + gn)       = make_float2(v0, v1);
                *(float2*)(o_f + (size_t)(gm + 8) * D_MODEL + gn) = make_float2(v2, v3);
            } else if (MODE < 3){
                int hh = gn >> 6, d = gn & 63;
                int b0i = gm >> 11, ss0 = gm & 2047;
                size_t off0 = (((size_t)(b0i * NH + hh)) * SEQ + ss0) * DH + d;
                split_store(o_h, o_l, off0, v0, v1);
                size_t off1 = off0 + 8 * DH;   // gm+8 -> s+8, same b
                split_store(o_h, o_l, off1, v2, v3);
            } else {
                int hh = gm >> 6, d = gm & 63;
                int b0i = gn >> 11, ss0 = gn & 2047;
                size_t off0 = (((size_t)(b0i * NH + hh)) * DH + d) * SEQ + ss0;
                split_store(o_h, o_l, off0, v0, v1);
                size_t off1 = off0 + 8 * SEQ;  // gm+8 -> d+8, same head
                split_store(o_h, o_l, off1, v2, v3);
            }
        }
    }
}

// ---------------- HMMA flash attention, 128q x 128k, P in registers -------
// 256 threads = 8 warps, warp = 16 q-rows x 128 cols. cp.async double buffer.
#define FK_H 0
#define FK_L 18432
#define FV_H 36864
#define FV_L 54272
#define FBUF 71680

__global__ void __launch_bounds__(256) mma_flash(
    const __half* __restrict__ qh, const __half* __restrict__ ql,
    const __half* __restrict__ kh, const __half* __restrict__ kl,
    const __half* __restrict__ vh, const __half* __restrict__ vl,
    __half* __restrict__ oh, __half* __restrict__ ol)
{
    extern __shared__ char smraw[];
    uint32_t smb = smem_u32(smraw);
    int tid = threadIdx.x, lane = tid & 31, w = tid >> 5;
    int q0 = blockIdx.x * 128, h = blockIdx.y, b = blockIdx.z;
    size_t hb = ((size_t)(b * NH + h)) * SEQ * DH;

    // K/V tile loader: K [128][64] stride 72h, V^T [64][128] stride 136h
    auto load_tile = [&](int kt, int bufo){
        #pragma unroll
        for (int i = 0; i < 4; i++){
            int idx = tid + i * 256;
            int row = idx >> 3, q = idx & 7;
            uint32_t d = smb + bufo + row * 144 + q * 16;
            const __half* g = kh + hb + (size_t)(kt * 128 + row) * DH + q * 8;
            cpasync16(d, g);
            cpasync16(d + (FK_L - FK_H), kl + hb + (size_t)(kt * 128 + row) * DH + q * 8);
        }
        #pragma unroll
        for (int i = 0; i < 4; i++){
            int idx = tid + i * 256;
            int dd = idx >> 4, q = idx & 15;
            uint32_t d = smb + bufo + FV_H + dd * 272 + q * 16;
            cpasync16(d, vh + hb + (size_t)dd * SEQ + kt * 128 + q * 8);
            cpasync16(d + (FV_L - FV_H), vl + hb + (size_t)dd * SEQ + kt * 128 + q * 8);
        }
    };

    // prologue: Q -> buf1 K region, tile0 -> buf0
    #pragma unroll
    for (int i = 0; i < 4; i++){
        int idx = tid + i * 256;
        int row = idx >> 3, q = idx & 7;
        uint32_t d = smb + FBUF + row * 144 + q * 16;
        cpasync16(d, qh + hb + (size_t)(q0 + row) * DH + q * 8);
        cpasync16(d + 18432, ql + hb + (size_t)(q0 + row) * DH + q * 8);
    }
    load_tile(0, 0);
    CP_COMMIT();
    CP_WAIT0();
    __syncthreads();

    // Q fragments to registers (warp w: rows 16w..16w+15)
    uint32_t qfh[4][4], qfl[4][4];
    #pragma unroll
    for (int f = 0; f < 4; f++){
        uint32_t a = (16 * w + (lane & 15)) * 144 + ((lane >> 4) * 8 + 16 * f) * 2;
        ldsm4(qfh[f], smb + FBUF + a);
        ldsm4(qfl[f], smb + FBUF + 18432 + a);
    }
    __syncthreads();
    load_tile(1, FBUF);
    CP_COMMIT();

    float o[8][4];
    #pragma unroll
    for (int j = 0; j < 8; j++)
        #pragma unroll
        for (int t = 0; t < 4; t++) o[j][t] = 0.f;
    float mi0 = -1e30f, mi1 = -1e30f, ls0 = 0.f, ls1 = 0.f;

    for (int kt = 0; kt < 16; kt++){
        int bufo = (kt & 1) * FBUF;
        if (kt > 0) CP_WAIT0();
        __syncthreads();
        if (kt + 1 < 16){ load_tile(kt + 1, ((kt + 1) & 1) * FBUF); CP_COMMIT(); }

        // S = Qh Kh + Ql Kh + Qh Kl
        float s[16][4];
        #pragma unroll
        for (int j = 0; j < 16; j++)
            #pragma unroll
            for (int t = 0; t < 4; t++) s[j][t] = 0.f;
        #pragma unroll
        for (int f = 0; f < 4; f++){
            #pragma unroll
            for (int jp = 0; jp < 8; jp++){
                uint32_t a = bufo + (16 * jp + (lane & 7) + ((lane >> 4) << 3)) * 144
                           + (16 * f + ((lane >> 3) & 1) * 8) * 2;
                uint32_t bh4[4], bl4[4];
                ldsm4(bh4, smb + a);
                ldsm4(bl4, smb + a + (FK_L - FK_H));
                mma16816(s[2*jp],   qfh[f], bh4);
                mma16816(s[2*jp],   qfl[f], bh4);
                mma16816(s[2*jp],   qfh[f], bl4);
                mma16816(s[2*jp+1], qfh[f], bh4 + 2);
                mma16816(s[2*jp+1], qfl[f], bh4 + 2);
                mma16816(s[2*jp+1], qfh[f], bl4 + 2);
            }
        }

        // online softmax (rows r=lane>>2 and r+8; quad = lanes xor 1,2)
        float m0 = mi0, m1 = mi1;
        #pragma unroll
        for (int j = 0; j < 16; j++){
            m0 = fmaxf(m0, fmaxf(s[j][0], s[j][1]));
            m1 = fmaxf(m1, fmaxf(s[j][2], s[j][3]));
        }
        m0 = fmaxf(m0, __shfl_xor_sync(0xffffffffu, m0, 1));
        m0 = fmaxf(m0, __shfl_xor_sync(0xffffffffu, m0, 2));
        m1 = fmaxf(m1, __shfl_xor_sync(0xffffffffu, m1, 1));
        m1 = fmaxf(m1, __shfl_xor_sync(0xffffffffu, m1, 2));
        float c0 = __expf(mi0 - m0), c1 = __expf(mi1 - m1);
        mi0 = m0; mi1 = m1;
        ls0 *= c0; ls1 *= c1;
        #pragma unroll
        for (int j = 0; j < 8; j++){
            o[j][0] *= c0; o[j][1] *= c0; o[j][2] *= c1; o[j][3] *= c1;
        }
        // exp -> fp16 P (li from rounded values for consistency)
        uint32_t pa[8][4];
        #pragma unroll
        for (int j = 0; j < 16; j++){
            float p0 = __expf(s[j][0] - m0), p1 = __expf(s[j][1] - m0);
            float p2 = __expf(s[j][2] - m1), p3 = __expf(s[j][3] - m1);
            uint32_t u01 = pack2(p0, p1), u23 = pack2(p2, p3);
            __half2 h01 = *(__half2*)&u01, h23 = *(__half2*)&u23;
            ls0 += __low2float(h01) + __high2float(h01);
            ls1 += __low2float(h23) + __high2float(h23);
            pa[j >> 1][(j & 1) * 2 + 0] = u01;
            pa[j >> 1][(j & 1) * 2 + 1] = u23;
        }
        // O += P Vh + P Vl
        #pragma unroll
        for (int f = 0; f < 8; f++){
            #pragma unroll
            for (int jp = 0; jp < 4; jp++){
                uint32_t a = bufo + FV_H + (16 * jp + (lane & 7) + ((lane >> 4) << 3)) * 272
                           + (16 * f + ((lane >> 3) & 1) * 8) * 2;
                uint32_t vh4[4], vl4[4];
                ldsm4(vh4, smb + a);
                ldsm4(vl4, smb + a + (FV_L - FV_H));
                mma16816(o[2*jp],   pa[f], vh4);
                mma16816(o[2*jp],   pa[f], vl4);
                mma16816(o[2*jp+1], pa[f], vh4 + 2);
                mma16816(o[2*jp+1], pa[f], vl4 + 2);
            }
        }
    }

    // epilogue
    ls0 += __shfl_xor_sync(0xffffffffu, ls0, 1);
    ls0 += __shfl_xor_sync(0xffffffffu, ls0, 2);
    ls1 += __shfl_xor_sync(0xffffffffu, ls1, 1);
    ls1 += __shfl_xor_sync(0xffffffffu, ls1, 2);
    float i0 = 1.f / ls0, i1 = 1.f / ls1;
    int r0 = q0 + 16 * w + (lane >> 2), r1 = r0 + 8;
    #pragma unroll
    for (int j = 0; j < 8; j++){
        int d = 8 * j + (lane & 3) * 2;
        size_t off0 = ((size_t)(b * SEQ + r0)) * D_MODEL + h * DH + d;
        size_t off1 = ((size_t)(b * SEQ + r1)) * D_MODEL + h * DH + d;
        split_store(oh, ol, off0, o[j][0] * i0, o[j][1] * i0);
        split_store(oh, ol, off1, o[j][2] * i1, o[j][3] * i1);
    }
}

// ---------------- launch ---------------------------------------------------
#define GEMM_SMEM  (2 * 3 * 10240)    // 61440
#define FLASH_SMEM (2 * FBUF)         // 143360

extern "C" void kernel_launch(void* const* d_in, const int* in_sizes, int n_in,
                              void* d_out, int out_size) {
    (void)in_sizes; (void)n_in; (void)out_size;
    const float* q  = (const float*)d_in[0];
    const float* k  = (const float*)d_in[1];
    const float* v  = (const float*)d_in[2];
    const float* wq = (const float*)d_in[3];
    const float* wk = (const float*)d_in[4];
    const float* wv = (const float*)d_in[5];
    const float* wo = (const float*)d_in[6];
    float* out = (float*)d_out;

    __half *tw, *xh, *xl, *pqh, *pql, *pkh, *pkl, *pvth, *pvtl, *pah, *pal;
    cudaGetSymbolAddress((void**)&tw,   g_tw);
    cudaGetSymbolAddress((void**)&xh,   g_xh);
    cudaGetSymbolAddress((void**)&xl,   g_xl);
    cudaGetSymbolAddress((void**)&pqh,  g_qh);
    cudaGetSymbolAddress((void**)&pql,  g_ql);
    cudaGetSymbolAddress((void**)&pkh,  g_kh);
    cudaGetSymbolAddress((void**)&pkl,  g_kl);
    cudaGetSymbolAddress((void**)&pvth, g_vth);
    cudaGetSymbolAddress((void**)&pvtl, g_vtl);
    cudaGetSymbolAddress((void**)&pah,  g_ah);
    cudaGetSymbolAddress((void**)&pal,  g_al);

    cudaFuncSetAttribute(mma_gemm<0>, cudaFuncAttributeMaxDynamicSharedMemorySize, GEMM_SMEM);
    cudaFuncSetAttribute(mma_gemm<1>, cudaFuncAttributeMaxDynamicSharedMemorySize, GEMM_SMEM);
    cudaFuncSetAttribute(mma_gemm<2>, cudaFuncAttributeMaxDynamicSharedMemorySize, GEMM_SMEM);
    cudaFuncSetAttribute(mma_gemm<3>, cudaFuncAttributeMaxDynamicSharedMemorySize, GEMM_SMEM);
    cudaFuncSetAttribute(mma_flash,   cudaFuncAttributeMaxDynamicSharedMemorySize, FLASH_SMEM);

    const size_t WSZ = (size_t)D_MODEL * D_MODEL;

    absmean_partial<<<dim3(64, 4), 256>>>(wq, wk, wv, wo);
    absmean_final<<<1, 32>>>();
    ternarize_h<<<dim3(4096, 4), 256>>>(wq, wk, wv, wo);

    // Q projection
    split_act<<<4096, 256>>>(q);
    mma_gemm<1><<<dim3(8, 32), 256, GEMM_SMEM>>>(xh, xl, tw + 0 * WSZ, nullptr,
                                                 pqh, pql, nullptr);
    // K projection
    split_act<<<4096, 256>>>(k);
    mma_gemm<2><<<dim3(8, 32), 256, GEMM_SMEM>>>(xh, xl, tw + 1 * WSZ, nullptr,
                                                 pkh, pkl, nullptr);
    // V projection (transposed output)
    split_act<<<4096, 256>>>(v);
    mma_gemm<3><<<dim3(32, 8), 256, GEMM_SMEM>>>(tw + 2 * WSZ, nullptr, xh, xl,
                                                 pvth, pvtl, nullptr);
    // attention
    mma_flash<<<dim3(SEQ / 128, NH, BATCH), 256, FLASH_SMEM>>>(
        pqh, pql, pkh, pkl, pvth, pvtl, pah, pal);
    // output projection
    mma_gemm<0><<<dim3(8, 32), 256, GEMM_SMEM>>>(pah, pal, tw + 3 * WSZ, nullptr,
                                                 nullptr, nullptr, out);
}